// round 8
// baseline (speedup 1.0000x reference)
#include <cuda_runtime.h>
#include <cstdint>

#define MAX_NODES 100000
#define MAX_EDGES 1600000
#define IN_C  32
#define HID_C 64
#define OUT_C 32
#define SCAN_CHUNK 1024
#define MAX_CHUNKS 128   // ceil(100000/1024)=98

// Scratch (__device__ globals: allocation-free rule)
__device__ __align__(16) float g_agg1[MAX_NODES * IN_C];    // raw sums
__device__ __align__(16) float g_hw  [MAX_NODES * OUT_C];   // relu(h) @ W2_l
__device__ __align__(16) float g_hr  [MAX_NODES * OUT_C];   // relu(h) @ W2_r
__device__ int g_deg   [MAX_NODES];
__device__ int g_rowptr[MAX_NODES + 1];
__device__ int g_cursor[MAX_NODES];
__device__ int g_col   [MAX_EDGES];
__device__ int g_chunkSum[MAX_CHUNKS];

// ---------------------------------------------------------------------------
// Packed f32x2 helpers (Blackwell FFMA2)
// ---------------------------------------------------------------------------
__device__ __forceinline__ void fma2(unsigned long long& d,
                                     unsigned long long a,
                                     unsigned long long b)
{
    asm("fma.rn.f32x2 %0, %1, %2, %0;" : "+l"(d) : "l"(a), "l"(b));
}
__device__ __forceinline__ unsigned long long pack2(float v)
{
    unsigned long long r;
    asm("mov.b64 %0, {%1, %1};" : "=l"(r) : "r"(__float_as_uint(v)));
    return r;
}
__device__ __forceinline__ float2 unpack2(unsigned long long v)
{
    float2 f;
    asm("mov.b64 {%0, %1}, %2;" : "=f"(f.x), "=f"(f.y) : "l"(v));
    return f;
}

// ---------------------------------------------------------------------------
// CSR build step 1: degree histogram over destinations (int4, 4 edges/thread)
// ---------------------------------------------------------------------------
__global__ void deg_count(const int* __restrict__ dst, int* __restrict__ deg,
                          int n_edges)
{
    int t = blockIdx.x * blockDim.x + threadIdx.x;
    int base = t * 4;
    if (base + 3 < n_edges) {
        int4 d4 = *(const int4*)(dst + base);
        atomicAdd(&deg[d4.x], 1);
        atomicAdd(&deg[d4.y], 1);
        atomicAdd(&deg[d4.z], 1);
        atomicAdd(&deg[d4.w], 1);
    } else {
        for (int e = base; e < n_edges; e++) atomicAdd(&deg[dst[e]], 1);
    }
}

// CSR step 2a: per-chunk exclusive scan. 256 thr x 4 elems.
__global__ void scan1(const int* __restrict__ deg, int* __restrict__ pref,
                      int* __restrict__ chunkSum, int n)
{
    __shared__ int sT[256];
    int chunk = blockIdx.x;
    int base  = chunk * SCAN_CHUNK;
    int t     = threadIdx.x;

    int v[4], s = 0;
#pragma unroll
    for (int j = 0; j < 4; j++) {
        int idx = base + t * 4 + j;
        v[j] = (idx < n) ? deg[idx] : 0;
        s += v[j];
    }
    sT[t] = s;
    __syncthreads();
#pragma unroll
    for (int off = 1; off < 256; off <<= 1) {
        int y = (t >= off) ? sT[t - off] : 0;
        __syncthreads();
        sT[t] += y;
        __syncthreads();
    }
    int excl = sT[t] - s;
#pragma unroll
    for (int j = 0; j < 4; j++) {
        int idx = base + t * 4 + j;
        if (idx < n) pref[idx] = excl;
        excl += v[j];
    }
    if (t == 255) chunkSum[chunk] = sT[255];
}

// CSR step 2b: add chunk offsets (computed per-block from shared chunkSum);
// init cursor; close row_ptr.
__global__ void scan2b(int* __restrict__ rowptr, int* __restrict__ cursor,
                       const int* __restrict__ chunkSum, int n, int nchunks)
{
    __shared__ int sCS[MAX_CHUNKS];
    for (int j = threadIdx.x; j < nchunks; j += blockDim.x)
        sCS[j] = chunkSum[j];
    __syncthreads();

    int i = blockIdx.x * blockDim.x + threadIdx.x;
    if (i < n) {
        int myChunk = i / SCAN_CHUNK;
        int off = 0;
        for (int j = 0; j < myChunk; j++) off += sCS[j];
        int v = rowptr[i] + off;
        rowptr[i] = v;
        cursor[i] = v;
    }
    if (i == 0) {
        int tot = 0;
        for (int j = 0; j < nchunks; j++) tot += sCS[j];
        rowptr[n] = tot;
    }
}

// CSR step 3: fill column (src) array. int4, 4 edges/thread.
__global__ void csr_fill(const int* __restrict__ src, const int* __restrict__ dst,
                         int* __restrict__ cursor, int* __restrict__ col,
                         int n_edges)
{
    int t = blockIdx.x * blockDim.x + threadIdx.x;
    int base = t * 4;
    if (base + 3 < n_edges) {
        int4 s4 = *(const int4*)(src + base);
        int4 d4 = *(const int4*)(dst + base);
        col[atomicAdd(&cursor[d4.x], 1)] = s4.x;
        col[atomicAdd(&cursor[d4.y], 1)] = s4.y;
        col[atomicAdd(&cursor[d4.z], 1)] = s4.z;
        col[atomicAdd(&cursor[d4.w], 1)] = s4.w;
    } else {
        for (int e = base; e < n_edges; e++)
            col[atomicAdd(&cursor[dst[e]], 1)] = src[e];
    }
}

// ---------------------------------------------------------------------------
// CSR gather, C=32: one warp per node; 8 edges per outer iter (2 load rounds
// back-to-back for MLP); cross-lane shfl reduction; no atomics.
//   FUSE_OUT=false: agg[n,:] = raw sum
//   FUSE_OUT=true : out[n,:] = sum/max(deg,1) + b + hr[n,:]
// ---------------------------------------------------------------------------
template <bool FUSE_OUT>
__global__ __launch_bounds__(256)
void gather32(const float* __restrict__ feat,
              const int* __restrict__ rowptr,
              const int* __restrict__ col,
              const float* __restrict__ b,
              const float* __restrict__ hr,
              float* __restrict__ outp,
              int n_nodes)
{
    int warp = (blockIdx.x * blockDim.x + threadIdx.x) >> 5;
    int lane = threadIdx.x & 31;
    if (warp >= n_nodes) return;
    int node = warp;

    int beg = rowptr[node];
    int end = rowptr[node + 1];

    int sub = lane >> 3;   // 0..3: which edge within a round
    int seg = lane & 7;    // float4 segment within the 32-float row

    float4 acc = {0.f, 0.f, 0.f, 0.f};
    for (int i = beg; i < end; i += 8) {
        int cv = (lane < 8 && i + lane < end) ? __ldg(col + i + lane) : 0;
        int c0 = __shfl_sync(0xffffffffu, cv, sub);
        int c1 = __shfl_sync(0xffffffffu, cv, 4 + sub);
        bool p0 = (i + sub) < end;
        bool p1 = (i + 4 + sub) < end;
        float4 v0 = {0,0,0,0}, v1 = {0,0,0,0};
        if (p0) v0 = *(const float4*)(feat + (long long)c0 * 32 + seg * 4);
        if (p1) v1 = *(const float4*)(feat + (long long)c1 * 32 + seg * 4);
        acc.x += v0.x + v1.x; acc.y += v0.y + v1.y;
        acc.z += v0.z + v1.z; acc.w += v0.w + v1.w;
    }
#pragma unroll
    for (int off = 8; off < 32; off <<= 1) {
        acc.x += __shfl_xor_sync(0xffffffffu, acc.x, off);
        acc.y += __shfl_xor_sync(0xffffffffu, acc.y, off);
        acc.z += __shfl_xor_sync(0xffffffffu, acc.z, off);
        acc.w += __shfl_xor_sync(0xffffffffu, acc.w, off);
    }
    if (lane < 8) {
        if (FUSE_OUT) {
            float inv = 1.0f / fmaxf((float)(end - beg), 1.0f);
            float4 bb = __ldg((const float4*)(b + seg * 4));
            float4 rr = *(const float4*)(hr + (long long)node * 32 + seg * 4);
            float4 o;
            o.x = acc.x * inv + bb.x + rr.x;
            o.y = acc.y * inv + bb.y + rr.y;
            o.z = acc.z * inv + bb.z + rr.z;
            o.w = acc.w * inv + bb.w + rr.w;
            *(float4*)(outp + (long long)node * 32 + seg * 4) = o;
        } else {
            *(float4*)(outp + (long long)node * 32 + seg * 4) = acc;
        }
    }
}

// ---------------------------------------------------------------------------
// Fused layer-1 transform + both layer-2 projections, in TWO h-halves to cap
// register pressure (~120 regs -> 2 CTAs/SM):
//   for half in {0,1}:
//     hhalf = relu( (agg1/deg) @ W1l[:,half] + b1[half] + x @ W1r[:,half] )
//     accL += hhalf @ W2l[half,:] ;  accR += hhalf @ W2r[half,:]
//   hw = accL ; hr = accR
// ---------------------------------------------------------------------------
__global__ __launch_bounds__(256, 2)
void transform_l1_fused(const float* __restrict__ x,
                        const float* __restrict__ agg,
                        const int* __restrict__ rowptr,
                        const float* __restrict__ Wl,
                        const float* __restrict__ b,
                        const float* __restrict__ Wr,
                        const float* __restrict__ W2l,
                        const float* __restrict__ W2r,
                        float* __restrict__ hw,
                        float* __restrict__ hr,
                        int n_nodes)
{
    __shared__ __align__(16) float sWl [IN_C  * HID_C];
    __shared__ __align__(16) float sWr [IN_C  * HID_C];
    __shared__ __align__(16) float sW2l[HID_C * OUT_C];
    __shared__ __align__(16) float sW2r[HID_C * OUT_C];
    __shared__ float sB[HID_C];

    for (int i = threadIdx.x * 4; i < IN_C * HID_C; i += 256 * 4) {
        *(float4*)&sWl[i] = *(const float4*)&Wl[i];
        *(float4*)&sWr[i] = *(const float4*)&Wr[i];
    }
    for (int i = threadIdx.x * 4; i < HID_C * OUT_C; i += 256 * 4) {
        *(float4*)&sW2l[i] = *(const float4*)&W2l[i];
        *(float4*)&sW2r[i] = *(const float4*)&W2r[i];
    }
    if (threadIdx.x < HID_C) sB[threadIdx.x] = b[threadIdx.x];
    __syncthreads();

    int node = blockIdx.x * 256 + threadIdx.x;
    if (node >= n_nodes) return;

    int deg = rowptr[node + 1] - rowptr[node];
    float inv = 1.0f / fmaxf((float)deg, 1.0f);

    const float4* arow = (const float4*)(agg + (long long)node * IN_C);
    const float4* xrow = (const float4*)(x   + (long long)node * IN_C);

    unsigned long long accL[OUT_C / 2], accR[OUT_C / 2];
#pragma unroll
    for (int i = 0; i < OUT_C / 2; i++) { accL[i] = 0ull; accR[i] = 0ull; }

#pragma unroll
    for (int half = 0; half < 2; half++) {
        const int cbase = half * 32;
        unsigned long long acc[16];
#pragma unroll
        for (int i = 0; i < 16; i++) acc[i] = 0ull;

        // (agg/deg) @ W1l[:, cbase..cbase+31]
#pragma unroll
        for (int kc = 0; kc < IN_C / 4; kc++) {
            float4 a4 = arow[kc];
            float av[4] = {a4.x * inv, a4.y * inv, a4.z * inv, a4.w * inv};
#pragma unroll
            for (int j = 0; j < 4; j++) {
                unsigned long long av2 = pack2(av[j]);
                const int k = kc * 4 + j;
#pragma unroll
                for (int c = 0; c < 32; c += 4) {
                    ulonglong2 w2 = *(const ulonglong2*)&sWl[k * HID_C + cbase + c];
                    fma2(acc[c / 2],     av2, w2.x);
                    fma2(acc[c / 2 + 1], av2, w2.y);
                }
            }
        }
        // x @ W1r[:, cbase..cbase+31]
#pragma unroll
        for (int kc = 0; kc < IN_C / 4; kc++) {
            float4 a4 = xrow[kc];
            float av[4] = {a4.x, a4.y, a4.z, a4.w};
#pragma unroll
            for (int j = 0; j < 4; j++) {
                unsigned long long av2 = pack2(av[j]);
                const int k = kc * 4 + j;
#pragma unroll
                for (int c = 0; c < 32; c += 4) {
                    ulonglong2 w2 = *(const ulonglong2*)&sWr[k * HID_C + cbase + c];
                    fma2(acc[c / 2],     av2, w2.x);
                    fma2(acc[c / 2 + 1], av2, w2.y);
                }
            }
        }

        // bias + relu -> 32 h-values for this half
        float hval[32];
#pragma unroll
        for (int c = 0; c < 32; c += 2) {
            float2 p = unpack2(acc[c / 2]);
            hval[c + 0] = fmaxf(p.x + sB[cbase + c + 0], 0.0f);
            hval[c + 1] = fmaxf(p.y + sB[cbase + c + 1], 0.0f);
        }

        // accumulate into both output projections
#pragma unroll
        for (int k2 = 0; k2 < 32; k2++) {
            unsigned long long av2 = pack2(hval[k2]);
            const int krow = cbase + k2;
#pragma unroll
            for (int c = 0; c < OUT_C; c += 4) {
                ulonglong2 wl = *(const ulonglong2*)&sW2l[krow * OUT_C + c];
                fma2(accL[c / 2],     av2, wl.x);
                fma2(accL[c / 2 + 1], av2, wl.y);
                ulonglong2 wr = *(const ulonglong2*)&sW2r[krow * OUT_C + c];
                fma2(accR[c / 2],     av2, wr.x);
                fma2(accR[c / 2 + 1], av2, wr.y);
            }
        }
    }

    float* hwrow = hw + (long long)node * OUT_C;
    float* hrrow = hr + (long long)node * OUT_C;
#pragma unroll
    for (int c = 0; c < OUT_C; c += 4) {
        float2 l0 = unpack2(accL[c / 2]);
        float2 l1 = unpack2(accL[c / 2 + 1]);
        float4 ol = {l0.x, l0.y, l1.x, l1.y};
        *(float4*)&hwrow[c] = ol;
        float2 r0 = unpack2(accR[c / 2]);
        float2 r1 = unpack2(accR[c / 2 + 1]);
        float4 orr = {r0.x, r0.y, r1.x, r1.y};
        *(float4*)&hrrow[c] = orr;
    }
}

// ---------------------------------------------------------------------------
// Launch
// ---------------------------------------------------------------------------
extern "C" void kernel_launch(void* const* d_in, const int* in_sizes, int n_in,
                              void* d_out, int out_size)
{
    const float* x    = (const float*)d_in[0];
    const int*   ei   = (const int*)d_in[1];     // [2, E] int32
    const float* W1l  = (const float*)d_in[2];
    const float* b1   = (const float*)d_in[3];
    const float* W1r  = (const float*)d_in[4];
    const float* W2l  = (const float*)d_in[5];
    const float* b2   = (const float*)d_in[6];
    const float* W2r  = (const float*)d_in[7];
    float*       out  = (float*)d_out;

    const int n_nodes = in_sizes[0] / IN_C;
    const int n_edges = in_sizes[1] / 2;
    const int nchunks = (n_nodes + SCAN_CHUNK - 1) / SCAN_CHUNK;

    const int* src = ei;
    const int* dst = ei + n_edges;

    float *agg1, *hw, *hr;
    int *deg, *rowptr, *cursor, *col, *chunkSum;
    cudaGetSymbolAddress((void**)&agg1,     g_agg1);
    cudaGetSymbolAddress((void**)&hw,       g_hw);
    cudaGetSymbolAddress((void**)&hr,       g_hr);
    cudaGetSymbolAddress((void**)&deg,      g_deg);
    cudaGetSymbolAddress((void**)&rowptr,   g_rowptr);
    cudaGetSymbolAddress((void**)&cursor,   g_cursor);
    cudaGetSymbolAddress((void**)&col,      g_col);
    cudaGetSymbolAddress((void**)&chunkSum, g_chunkSum);

    // --- CSR build (same graph reused by both layers) ---
    cudaMemsetAsync(deg, 0, (size_t)n_nodes * sizeof(int));
    {
        int t = (n_edges + 3) / 4;
        deg_count<<<(t + 255) / 256, 256>>>(dst, deg, n_edges);
    }
    scan1<<<nchunks, 256>>>(deg, rowptr, chunkSum, n_nodes);
    scan2b<<<(n_nodes + 255) / 256, 256>>>(rowptr, cursor, chunkSum, n_nodes, nchunks);
    {
        int t = (n_edges + 3) / 4;
        csr_fill<<<(t + 255) / 256, 256>>>(src, dst, cursor, col, n_edges);
    }

    const int gather_blocks = (n_nodes * 32 + 255) / 256;

    // Layer 1 aggregate: gather raw sums
    gather32<false><<<gather_blocks, 256>>>(x, rowptr, col, nullptr, nullptr,
                                            agg1, n_nodes);

    // Fused: layer-1 transform + hw (=h@W2l) + hr (=h@W2r)
    transform_l1_fused<<<(n_nodes + 255) / 256, 256>>>(
        x, agg1, rowptr, W1l, b1, W1r, W2l, W2r, hw, hr, n_nodes);

    // Layer 2 aggregate fused with final combine
    gather32<true><<<gather_blocks, 256>>>(hw, rowptr, col, b2, hr,
                                           out, n_nodes);
}

// round 9
// speedup vs baseline: 1.0060x; 1.0060x over previous
#include <cuda_runtime.h>
#include <cstdint>

#define MAX_NODES 100000
#define IN_C  32
#define HID_C 64
#define OUT_C 32

// Scratch (__device__ globals: allocation-free rule)
__device__ __align__(16) float g_agg1[MAX_NODES * IN_C];    // 12.8 MB
__device__ __align__(16) float g_hw  [MAX_NODES * OUT_C];   // relu(h) @ W2_l
__device__ __align__(16) float g_hr  [MAX_NODES * OUT_C];   // relu(h) @ W2_r
__device__ __align__(16) float g_agg2[MAX_NODES * OUT_C];
__device__               float g_cnt [MAX_NODES];

// ---------------------------------------------------------------------------
// Packed f32x2 helpers (Blackwell FFMA2)
// ---------------------------------------------------------------------------
__device__ __forceinline__ void fma2(unsigned long long& d,
                                     unsigned long long a,
                                     unsigned long long b)
{
    asm("fma.rn.f32x2 %0, %1, %2, %0;" : "+l"(d) : "l"(a), "l"(b));
}
__device__ __forceinline__ unsigned long long pack2(float v)
{
    unsigned long long r;
    asm("mov.b64 %0, {%1, %1};" : "=l"(r) : "r"(__float_as_uint(v)));
    return r;
}
__device__ __forceinline__ float2 unpack2(unsigned long long v)
{
    float2 f;
    asm("mov.b64 {%0, %1}, %2;" : "=f"(f.x), "=f"(f.y) : "l"(v));
    return f;
}

// ---------------------------------------------------------------------------
// Warp-shuffle scatter-add, C=32. Each warp owns 32 edges: every lane loads
// its own edge's (src,dst) ONCE (coalesced), then 8 passes of 4 edges x 8
// float4 segments; indices distributed via shfl (ALU pipe, off the LSU).
// ---------------------------------------------------------------------------
template <bool COUNT>
__global__ void scatter32(const float* __restrict__ feat,
                          const int* __restrict__ ei,
                          float* __restrict__ agg,
                          float* __restrict__ cnt,
                          int n_edges)
{
    int warp = (blockIdx.x * blockDim.x + threadIdx.x) >> 5;
    int lane = threadIdx.x & 31;
    int base = warp * 32;
    if (base >= n_edges) return;

    int my_e   = base + lane;
    bool has   = my_e < n_edges;
    int e_clmp = has ? my_e : (n_edges - 1);
    int my_src = __ldg(ei + e_clmp);
    int my_dst = __ldg(ei + n_edges + e_clmp);

    if (COUNT && has) atomicAdd(&cnt[my_dst], 1.0f);

    int seg = lane & 7;   // float4 segment within the 32-float row
    int sub = lane >> 3;  // which of 4 edges this pass

#pragma unroll
    for (int pass = 0; pass < 8; pass++) {
        int eslot = pass * 4 + sub;
        int src = __shfl_sync(0xffffffffu, my_src, eslot);
        int dst = __shfl_sync(0xffffffffu, my_dst, eslot);
        if (base + eslot < n_edges) {
            float4 v = *(const float4*)(feat + (long long)src * 32 + seg * 4);
            atomicAdd((float4*)(agg + (long long)dst * 32 + seg * 4), v);
        }
    }
}

// ---------------------------------------------------------------------------
// Fused layer-1 transform + both layer-2 projections, in TWO h-halves to cap
// register pressure (~120 regs -> 2 CTAs/SM):
//   for half in {0,1}:
//     hhalf = relu( (agg1/max(cnt,1)) @ W1l[:,half] + b1[half] + x @ W1r[:,half] )
//     accL += hhalf @ W2l[half,:] ;  accR += hhalf @ W2r[half,:]
//   hw = accL ; hr = accR          (h never touches gmem)
// ---------------------------------------------------------------------------
__global__ __launch_bounds__(256, 2)
void transform_l1_fused(const float* __restrict__ x,
                        const float* __restrict__ agg,
                        const float* __restrict__ cnt,
                        const float* __restrict__ Wl,
                        const float* __restrict__ b,
                        const float* __restrict__ Wr,
                        const float* __restrict__ W2l,
                        const float* __restrict__ W2r,
                        float* __restrict__ hw,
                        float* __restrict__ hr,
                        int n_nodes)
{
    __shared__ __align__(16) float sWl [IN_C  * HID_C];
    __shared__ __align__(16) float sWr [IN_C  * HID_C];
    __shared__ __align__(16) float sW2l[HID_C * OUT_C];
    __shared__ __align__(16) float sW2r[HID_C * OUT_C];
    __shared__ float sB[HID_C];

    for (int i = threadIdx.x * 4; i < IN_C * HID_C; i += 256 * 4) {
        *(float4*)&sWl[i] = *(const float4*)&Wl[i];
        *(float4*)&sWr[i] = *(const float4*)&Wr[i];
    }
    for (int i = threadIdx.x * 4; i < HID_C * OUT_C; i += 256 * 4) {
        *(float4*)&sW2l[i] = *(const float4*)&W2l[i];
        *(float4*)&sW2r[i] = *(const float4*)&W2r[i];
    }
    if (threadIdx.x < HID_C) sB[threadIdx.x] = b[threadIdx.x];
    __syncthreads();

    int node = blockIdx.x * 256 + threadIdx.x;
    if (node >= n_nodes) return;

    float inv = 1.0f / fmaxf(cnt[node], 1.0f);

    const float4* arow = (const float4*)(agg + (long long)node * IN_C);
    const float4* xrow = (const float4*)(x   + (long long)node * IN_C);

    unsigned long long accL[OUT_C / 2], accR[OUT_C / 2];
#pragma unroll
    for (int i = 0; i < OUT_C / 2; i++) { accL[i] = 0ull; accR[i] = 0ull; }

#pragma unroll
    for (int half = 0; half < 2; half++) {
        const int cbase = half * 32;
        unsigned long long acc[16];
#pragma unroll
        for (int i = 0; i < 16; i++) acc[i] = 0ull;

        // (agg/cnt) @ W1l[:, cbase..cbase+31]
#pragma unroll
        for (int kc = 0; kc < IN_C / 4; kc++) {
            float4 a4 = arow[kc];
            float av[4] = {a4.x * inv, a4.y * inv, a4.z * inv, a4.w * inv};
#pragma unroll
            for (int j = 0; j < 4; j++) {
                unsigned long long av2 = pack2(av[j]);
                const int k = kc * 4 + j;
#pragma unroll
                for (int c = 0; c < 32; c += 4) {
                    ulonglong2 w2 = *(const ulonglong2*)&sWl[k * HID_C + cbase + c];
                    fma2(acc[c / 2],     av2, w2.x);
                    fma2(acc[c / 2 + 1], av2, w2.y);
                }
            }
        }
        // x @ W1r[:, cbase..cbase+31]
#pragma unroll
        for (int kc = 0; kc < IN_C / 4; kc++) {
            float4 a4 = xrow[kc];
            float av[4] = {a4.x, a4.y, a4.z, a4.w};
#pragma unroll
            for (int j = 0; j < 4; j++) {
                unsigned long long av2 = pack2(av[j]);
                const int k = kc * 4 + j;
#pragma unroll
                for (int c = 0; c < 32; c += 4) {
                    ulonglong2 w2 = *(const ulonglong2*)&sWr[k * HID_C + cbase + c];
                    fma2(acc[c / 2],     av2, w2.x);
                    fma2(acc[c / 2 + 1], av2, w2.y);
                }
            }
        }

        // bias + relu -> 32 h-values of this half, then fold into projections
        float hval[32];
#pragma unroll
        for (int c = 0; c < 32; c += 2) {
            float2 p = unpack2(acc[c / 2]);
            hval[c + 0] = fmaxf(p.x + sB[cbase + c + 0], 0.0f);
            hval[c + 1] = fmaxf(p.y + sB[cbase + c + 1], 0.0f);
        }
#pragma unroll
        for (int k2 = 0; k2 < 32; k2++) {
            unsigned long long av2 = pack2(hval[k2]);
            const int krow = cbase + k2;
#pragma unroll
            for (int c = 0; c < OUT_C; c += 4) {
                ulonglong2 wl = *(const ulonglong2*)&sW2l[krow * OUT_C + c];
                fma2(accL[c / 2],     av2, wl.x);
                fma2(accL[c / 2 + 1], av2, wl.y);
                ulonglong2 wr = *(const ulonglong2*)&sW2r[krow * OUT_C + c];
                fma2(accR[c / 2],     av2, wr.x);
                fma2(accR[c / 2 + 1], av2, wr.y);
            }
        }
    }

    float* hwrow = hw + (long long)node * OUT_C;
    float* hrrow = hr + (long long)node * OUT_C;
#pragma unroll
    for (int c = 0; c < OUT_C; c += 4) {
        float2 l0 = unpack2(accL[c / 2]);
        float2 l1 = unpack2(accL[c / 2 + 1]);
        float4 ol = {l0.x, l0.y, l1.x, l1.y};
        *(float4*)&hwrow[c] = ol;
        float2 r0 = unpack2(accR[c / 2]);
        float2 r1 = unpack2(accR[c / 2 + 1]);
        float4 orr = {r0.x, r0.y, r1.x, r1.y};
        *(float4*)&hrrow[c] = orr;
    }
}

// ---------------------------------------------------------------------------
// Final elementwise: out[n,c] = agg2[n,c]/max(cnt[n],1) + b2[c] + hr[n,c]
// ---------------------------------------------------------------------------
__global__ __launch_bounds__(256)
void final_add(const float* __restrict__ agg,
               const float* __restrict__ cnt,
               const float* __restrict__ b,
               const float* __restrict__ hr,
               float* __restrict__ out,
               int n_nodes)
{
    __shared__ float sB[OUT_C];
    if (threadIdx.x < OUT_C) sB[threadIdx.x] = b[threadIdx.x];
    __syncthreads();

    int t = blockIdx.x * 256 + threadIdx.x;
    int total = n_nodes * (OUT_C / 4);
    if (t >= total) return;

    int node = t >> 3;
    int seg  = t & 7;

    float inv = 1.0f / fmaxf(cnt[node], 1.0f);
    float4 a = *(const float4*)(agg + (long long)node * OUT_C + seg * 4);
    float4 r = *(const float4*)(hr  + (long long)node * OUT_C + seg * 4);
    float4 o;
    o.x = a.x * inv + sB[seg * 4 + 0] + r.x;
    o.y = a.y * inv + sB[seg * 4 + 1] + r.y;
    o.z = a.z * inv + sB[seg * 4 + 2] + r.z;
    o.w = a.w * inv + sB[seg * 4 + 3] + r.w;
    *(float4*)(out + (long long)node * OUT_C + seg * 4) = o;
}

// ---------------------------------------------------------------------------
// Launch
// ---------------------------------------------------------------------------
extern "C" void kernel_launch(void* const* d_in, const int* in_sizes, int n_in,
                              void* d_out, int out_size)
{
    const float* x    = (const float*)d_in[0];
    const int*   ei   = (const int*)d_in[1];
    const float* W1l  = (const float*)d_in[2];
    const float* b1   = (const float*)d_in[3];
    const float* W1r  = (const float*)d_in[4];
    const float* W2l  = (const float*)d_in[5];
    const float* b2   = (const float*)d_in[6];
    const float* W2r  = (const float*)d_in[7];
    float*       out  = (float*)d_out;

    const int n_nodes = in_sizes[0] / IN_C;
    const int n_edges = in_sizes[1] / 2;

    float *agg1, *hw, *hr, *agg2, *cnt;
    cudaGetSymbolAddress((void**)&agg1, g_agg1);
    cudaGetSymbolAddress((void**)&hw,   g_hw);
    cudaGetSymbolAddress((void**)&hr,   g_hr);
    cudaGetSymbolAddress((void**)&agg2, g_agg2);
    cudaGetSymbolAddress((void**)&cnt,  g_cnt);

    cudaMemsetAsync(agg1, 0, (size_t)n_nodes * IN_C  * sizeof(float));
    cudaMemsetAsync(agg2, 0, (size_t)n_nodes * OUT_C * sizeof(float));
    cudaMemsetAsync(cnt,  0, (size_t)n_nodes * sizeof(float));

    const int warps  = (n_edges + 31) / 32;
    const int blocks_sc = (warps * 32 + 255) / 256;

    // Layer 1 aggregate (32-dim) + degree count
    scatter32<true><<<blocks_sc, 256>>>(x, ei, agg1, cnt, n_edges);

    // Fused: layer-1 transform + hw (=h@W2l) + hr (=h@W2r); h stays in regs
    {
        int blocks = (n_nodes + 255) / 256;
        transform_l1_fused<<<blocks, 256>>>(x, agg1, cnt, W1l, b1, W1r,
                                            W2l, W2r, hw, hr, n_nodes);
    }

    // Layer 2 aggregate (32-dim)
    scatter32<false><<<blocks_sc, 256>>>(hw, ei, agg2, nullptr, n_edges);

    // Final elementwise combine
    {
        int total = n_nodes * (OUT_C / 4);
        int blocks = (total + 255) / 256;
        final_add<<<blocks, 256>>>(agg2, cnt, b2, hr, out, n_nodes);
    }
}

// round 10
// speedup vs baseline: 1.3916x; 1.3832x over previous
#include <cuda_runtime.h>
#include <cstdint>

#define MAX_NODES 100000
#define IN_C  32
#define HID_C 64
#define OUT_C 32

// Scratch (__device__ globals: allocation-free rule)
__device__ __align__(16) float g_agg1[MAX_NODES * IN_C];    // 12.8 MB
__device__ __align__(16) float g_hw  [MAX_NODES * OUT_C];   // relu(h) @ W2_l
__device__ __align__(16) float g_hr  [MAX_NODES * OUT_C];   // relu(h) @ W2_r
__device__ __align__(16) float g_agg2[MAX_NODES * OUT_C];
__device__               float g_cnt [MAX_NODES];

// ---------------------------------------------------------------------------
// Packed f32x2 helpers (Blackwell FFMA2)
// ---------------------------------------------------------------------------
__device__ __forceinline__ void fma2(unsigned long long& d,
                                     unsigned long long a,
                                     unsigned long long b)
{
    asm("fma.rn.f32x2 %0, %1, %2, %0;" : "+l"(d) : "l"(a), "l"(b));
}
__device__ __forceinline__ unsigned long long pack2(float v)
{
    unsigned long long r;
    asm("mov.b64 %0, {%1, %1};" : "=l"(r) : "r"(__float_as_uint(v)));
    return r;
}
__device__ __forceinline__ float2 unpack2(unsigned long long v)
{
    float2 f;
    asm("mov.b64 {%0, %1}, %2;" : "=f"(f.x), "=f"(f.y) : "l"(v));
    return f;
}

// ---------------------------------------------------------------------------
// Warp-shuffle scatter-add, C=32 (unchanged from the 164us best).
// ---------------------------------------------------------------------------
template <bool COUNT>
__global__ void scatter32(const float* __restrict__ feat,
                          const int* __restrict__ ei,
                          float* __restrict__ agg,
                          float* __restrict__ cnt,
                          int n_edges)
{
    int warp = (blockIdx.x * blockDim.x + threadIdx.x) >> 5;
    int lane = threadIdx.x & 31;
    int base = warp * 32;
    if (base >= n_edges) return;

    int my_e   = base + lane;
    bool has   = my_e < n_edges;
    int e_clmp = has ? my_e : (n_edges - 1);
    int my_src = __ldg(ei + e_clmp);
    int my_dst = __ldg(ei + n_edges + e_clmp);

    if (COUNT && has) atomicAdd(&cnt[my_dst], 1.0f);

    int seg = lane & 7;
    int sub = lane >> 3;

#pragma unroll
    for (int pass = 0; pass < 8; pass++) {
        int eslot = pass * 4 + sub;
        int src = __shfl_sync(0xffffffffu, my_src, eslot);
        int dst = __shfl_sync(0xffffffffu, my_dst, eslot);
        if (base + eslot < n_edges) {
            float4 v = *(const float4*)(feat + (long long)src * 32 + seg * 4);
            atomicAdd((float4*)(agg + (long long)dst * 32 + seg * 4), v);
        }
    }
}

// ---------------------------------------------------------------------------
// Fused layer-1 transform + both layer-2 projections, two h-halves.
// NO min-blocks clause (R9 lesson: forcing 2 blocks spilled ~30 regs).
// blockDim=128: at ~160 natural regs, 3 CTAs/SM -> 12 warps/SM.
// ---------------------------------------------------------------------------
__global__ __launch_bounds__(128)
void transform_l1_fused(const float* __restrict__ x,
                        const float* __restrict__ agg,
                        const float* __restrict__ cnt,
                        const float* __restrict__ Wl,
                        const float* __restrict__ b,
                        const float* __restrict__ Wr,
                        const float* __restrict__ W2l,
                        const float* __restrict__ W2r,
                        float* __restrict__ hw,
                        float* __restrict__ hr,
                        int n_nodes)
{
    __shared__ __align__(16) float sWl [IN_C  * HID_C];
    __shared__ __align__(16) float sWr [IN_C  * HID_C];
    __shared__ __align__(16) float sW2l[HID_C * OUT_C];
    __shared__ __align__(16) float sW2r[HID_C * OUT_C];
    __shared__ float sB[HID_C];

    for (int i = threadIdx.x * 4; i < IN_C * HID_C; i += 128 * 4) {
        *(float4*)&sWl[i] = *(const float4*)&Wl[i];
        *(float4*)&sWr[i] = *(const float4*)&Wr[i];
    }
    for (int i = threadIdx.x * 4; i < HID_C * OUT_C; i += 128 * 4) {
        *(float4*)&sW2l[i] = *(const float4*)&W2l[i];
        *(float4*)&sW2r[i] = *(const float4*)&W2r[i];
    }
    if (threadIdx.x < HID_C) sB[threadIdx.x] = b[threadIdx.x];
    __syncthreads();

    int node = blockIdx.x * 128 + threadIdx.x;
    if (node >= n_nodes) return;

    float inv = 1.0f / fmaxf(cnt[node], 1.0f);

    const float4* arow = (const float4*)(agg + (long long)node * IN_C);
    const float4* xrow = (const float4*)(x   + (long long)node * IN_C);

    unsigned long long accL[OUT_C / 2], accR[OUT_C / 2];
#pragma unroll
    for (int i = 0; i < OUT_C / 2; i++) { accL[i] = 0ull; accR[i] = 0ull; }

#pragma unroll
    for (int half = 0; half < 2; half++) {
        const int cbase = half * 32;
        unsigned long long acc[16];
#pragma unroll
        for (int i = 0; i < 16; i++) acc[i] = 0ull;

        // (agg/cnt) @ W1l[:, half]
#pragma unroll
        for (int kc = 0; kc < IN_C / 4; kc++) {
            float4 a4 = arow[kc];
            float av[4] = {a4.x * inv, a4.y * inv, a4.z * inv, a4.w * inv};
#pragma unroll
            for (int j = 0; j < 4; j++) {
                unsigned long long av2 = pack2(av[j]);
                const int k = kc * 4 + j;
#pragma unroll
                for (int c = 0; c < 32; c += 4) {
                    ulonglong2 w2 = *(const ulonglong2*)&sWl[k * HID_C + cbase + c];
                    fma2(acc[c / 2],     av2, w2.x);
                    fma2(acc[c / 2 + 1], av2, w2.y);
                }
            }
        }
        // x @ W1r[:, half]
#pragma unroll
        for (int kc = 0; kc < IN_C / 4; kc++) {
            float4 a4 = xrow[kc];
            float av[4] = {a4.x, a4.y, a4.z, a4.w};
#pragma unroll
            for (int j = 0; j < 4; j++) {
                unsigned long long av2 = pack2(av[j]);
                const int k = kc * 4 + j;
#pragma unroll
                for (int c = 0; c < 32; c += 4) {
                    ulonglong2 w2 = *(const ulonglong2*)&sWr[k * HID_C + cbase + c];
                    fma2(acc[c / 2],     av2, w2.x);
                    fma2(acc[c / 2 + 1], av2, w2.y);
                }
            }
        }

        // bias + relu -> this half's h values; fold into both projections
        float hval[32];
#pragma unroll
        for (int c = 0; c < 32; c += 2) {
            float2 p = unpack2(acc[c / 2]);
            hval[c + 0] = fmaxf(p.x + sB[cbase + c + 0], 0.0f);
            hval[c + 1] = fmaxf(p.y + sB[cbase + c + 1], 0.0f);
        }
#pragma unroll
        for (int k2 = 0; k2 < 32; k2++) {
            unsigned long long av2 = pack2(hval[k2]);
            const int krow = cbase + k2;
#pragma unroll
            for (int c = 0; c < OUT_C; c += 4) {
                ulonglong2 wl = *(const ulonglong2*)&sW2l[krow * OUT_C + c];
                fma2(accL[c / 2],     av2, wl.x);
                fma2(accL[c / 2 + 1], av2, wl.y);
                ulonglong2 wr = *(const ulonglong2*)&sW2r[krow * OUT_C + c];
                fma2(accR[c / 2],     av2, wr.x);
                fma2(accR[c / 2 + 1], av2, wr.y);
            }
        }
    }

    float* hwrow = hw + (long long)node * OUT_C;
    float* hrrow = hr + (long long)node * OUT_C;
#pragma unroll
    for (int c = 0; c < OUT_C; c += 4) {
        float2 l0 = unpack2(accL[c / 2]);
        float2 l1 = unpack2(accL[c / 2 + 1]);
        float4 ol = {l0.x, l0.y, l1.x, l1.y};
        *(float4*)&hwrow[c] = ol;
        float2 r0 = unpack2(accR[c / 2]);
        float2 r1 = unpack2(accR[c / 2 + 1]);
        float4 orr = {r0.x, r0.y, r1.x, r1.y};
        *(float4*)&hrrow[c] = orr;
    }
}

// ---------------------------------------------------------------------------
// Final elementwise: out[n,c] = agg2[n,c]/max(cnt[n],1) + b2[c] + hr[n,c]
// ---------------------------------------------------------------------------
__global__ __launch_bounds__(256)
void final_add(const float* __restrict__ agg,
               const float* __restrict__ cnt,
               const float* __restrict__ b,
               const float* __restrict__ hr,
               float* __restrict__ out,
               int n_nodes)
{
    __shared__ float sB[OUT_C];
    if (threadIdx.x < OUT_C) sB[threadIdx.x] = b[threadIdx.x];
    __syncthreads();

    int t = blockIdx.x * 256 + threadIdx.x;
    int total = n_nodes * (OUT_C / 4);
    if (t >= total) return;

    int node = t >> 3;
    int seg  = t & 7;

    float inv = 1.0f / fmaxf(cnt[node], 1.0f);
    float4 a = *(const float4*)(agg + (long long)node * OUT_C + seg * 4);
    float4 r = *(const float4*)(hr  + (long long)node * OUT_C + seg * 4);
    float4 o;
    o.x = a.x * inv + sB[seg * 4 + 0] + r.x;
    o.y = a.y * inv + sB[seg * 4 + 1] + r.y;
    o.z = a.z * inv + sB[seg * 4 + 2] + r.z;
    o.w = a.w * inv + sB[seg * 4 + 3] + r.w;
    *(float4*)(out + (long long)node * OUT_C + seg * 4) = o;
}

// ---------------------------------------------------------------------------
// Launch
// ---------------------------------------------------------------------------
extern "C" void kernel_launch(void* const* d_in, const int* in_sizes, int n_in,
                              void* d_out, int out_size)
{
    const float* x    = (const float*)d_in[0];
    const int*   ei   = (const int*)d_in[1];
    const float* W1l  = (const float*)d_in[2];
    const float* b1   = (const float*)d_in[3];
    const float* W1r  = (const float*)d_in[4];
    const float* W2l  = (const float*)d_in[5];
    const float* b2   = (const float*)d_in[6];
    const float* W2r  = (const float*)d_in[7];
    float*       out  = (float*)d_out;

    const int n_nodes = in_sizes[0] / IN_C;
    const int n_edges = in_sizes[1] / 2;

    float *agg1, *hw, *hr, *agg2, *cnt;
    cudaGetSymbolAddress((void**)&agg1, g_agg1);
    cudaGetSymbolAddress((void**)&hw,   g_hw);
    cudaGetSymbolAddress((void**)&hr,   g_hr);
    cudaGetSymbolAddress((void**)&agg2, g_agg2);
    cudaGetSymbolAddress((void**)&cnt,  g_cnt);

    cudaMemsetAsync(agg1, 0, (size_t)n_nodes * IN_C  * sizeof(float));
    cudaMemsetAsync(agg2, 0, (size_t)n_nodes * OUT_C * sizeof(float));
    cudaMemsetAsync(cnt,  0, (size_t)n_nodes * sizeof(float));

    const int warps  = (n_edges + 31) / 32;
    const int blocks_sc = (warps * 32 + 255) / 256;

    // Layer 1 aggregate (32-dim) + degree count
    scatter32<true><<<blocks_sc, 256>>>(x, ei, agg1, cnt, n_edges);

    // Fused: layer-1 transform + hw (=h@W2l) + hr (=h@W2r); h stays in regs
    {
        int blocks = (n_nodes + 127) / 128;
        transform_l1_fused<<<blocks, 128>>>(x, agg1, cnt, W1l, b1, W1r,
                                            W2l, W2r, hw, hr, n_nodes);
    }

    // Layer 2 aggregate (32-dim)
    scatter32<false><<<blocks_sc, 256>>>(hw, ei, agg2, nullptr, n_edges);

    // Final elementwise combine
    {
        int total = n_nodes * (OUT_C / 4);
        int blocks = (total + 255) / 256;
        final_add<<<blocks, 256>>>(agg2, cnt, b2, hr, out, n_nodes);
    }
}

// round 11
// speedup vs baseline: 1.7200x; 1.2360x over previous
#include <cuda_runtime.h>
#include <cstdint>

#define MAX_NODES 100000
#define IN_C  32
#define HID_C 64
#define OUT_C 32
#define NT 128          // nodes per transform block
#define STRIDE 132      // padded shared row stride (floats), 16B-aligned rows

// Scratch (__device__ globals: allocation-free rule)
__device__ __align__(16) float g_agg1[MAX_NODES * IN_C];    // 12.8 MB
__device__ __align__(16) float g_hw  [MAX_NODES * OUT_C];   // relu(h) @ W2_l
__device__ __align__(16) float g_hr  [MAX_NODES * OUT_C];   // relu(h) @ W2_r
__device__ __align__(16) float g_agg2[MAX_NODES * OUT_C];
__device__               float g_cnt [MAX_NODES];

// ---------------------------------------------------------------------------
// Packed f32x2 helpers (Blackwell FFMA2)
// ---------------------------------------------------------------------------
__device__ __forceinline__ void fma2(unsigned long long& d,
                                     unsigned long long a,
                                     unsigned long long b)
{
    asm("fma.rn.f32x2 %0, %1, %2, %0;" : "+l"(d) : "l"(a), "l"(b));
}
__device__ __forceinline__ unsigned long long pack2(float v)
{
    unsigned long long r;
    asm("mov.b64 %0, {%1, %1};" : "=l"(r) : "r"(__float_as_uint(v)));
    return r;
}
__device__ __forceinline__ float2 unpack2(unsigned long long v)
{
    float2 f;
    asm("mov.b64 {%0, %1}, %2;" : "=f"(f.x), "=f"(f.y) : "l"(v));
    return f;
}

// ---------------------------------------------------------------------------
// Warp-shuffle scatter-add, C=32 (unchanged from the 164us best).
// ---------------------------------------------------------------------------
template <bool COUNT>
__global__ void scatter32(const float* __restrict__ feat,
                          const int* __restrict__ ei,
                          float* __restrict__ agg,
                          float* __restrict__ cnt,
                          int n_edges)
{
    int warp = (blockIdx.x * blockDim.x + threadIdx.x) >> 5;
    int lane = threadIdx.x & 31;
    int base = warp * 32;
    if (base >= n_edges) return;

    int my_e   = base + lane;
    bool has   = my_e < n_edges;
    int e_clmp = has ? my_e : (n_edges - 1);
    int my_src = __ldg(ei + e_clmp);
    int my_dst = __ldg(ei + n_edges + e_clmp);

    if (COUNT && has) atomicAdd(&cnt[my_dst], 1.0f);

    int seg = lane & 7;
    int sub = lane >> 3;

#pragma unroll
    for (int pass = 0; pass < 8; pass++) {
        int eslot = pass * 4 + sub;
        int src = __shfl_sync(0xffffffffu, my_src, eslot);
        int dst = __shfl_sync(0xffffffffu, my_dst, eslot);
        if (base + eslot < n_edges) {
            float4 v = *(const float4*)(feat + (long long)src * 32 + seg * 4);
            atomicAdd((float4*)(agg + (long long)dst * 32 + seg * 4), v);
        }
    }
}

// ---------------------------------------------------------------------------
// Tiled fused transform. Block = 128 nodes, 256 threads.
// Warp w owns output channels [8w, 8w+8); lane owns nodes [4*lane, 4*lane+4).
//   GEMM1: h = relu( (agg1/deg) @ W1l + b1 + x @ W1r )   (h -> shared only)
//   GEMM2: [hw | hr] = h @ [W2l | W2r]                   (64->64 concat)
// Inputs staged transposed [k][node] in shared (pre-scaled); weights are
// warp-broadcast LDS.128; input LDS.128 covers 4 nodes.
// ---------------------------------------------------------------------------
__global__ __launch_bounds__(256)
void transform_l1_tiled(const float* __restrict__ x,
                        const float* __restrict__ agg,
                        const float* __restrict__ cnt,
                        const float* __restrict__ W1l,
                        const float* __restrict__ b1,
                        const float* __restrict__ W1r,
                        const float* __restrict__ W2l,
                        const float* __restrict__ W2r,
                        float* __restrict__ hw,
                        float* __restrict__ hr,
                        int n_nodes)
{
    extern __shared__ __align__(16) float smem[];
    float* sAgg = smem;                          // [32][STRIDE]
    float* sX   = smem + IN_C * STRIDE;          // [32][STRIDE]
    float* sH   = smem;                          // [64][STRIDE] (overlay, same size)
    float* sW1l = smem + HID_C * STRIDE;         // 32*64
    float* sW1r = sW1l + IN_C * HID_C;           // 32*64
    float* sW2  = sW1r + IN_C * HID_C;           // 64*64 = [W2l | W2r]
    float* sB   = sW2  + HID_C * 64;             // 64

    int tid  = threadIdx.x;
    int warp = tid >> 5;
    int lane = tid & 31;

    // Stage weights
    for (int i = tid * 4; i < IN_C * HID_C; i += 256 * 4) {
        *(float4*)&sW1l[i] = *(const float4*)&W1l[i];
        *(float4*)&sW1r[i] = *(const float4*)&W1r[i];
    }
    for (int i = tid * 4; i < HID_C * 64; i += 256 * 4) {
        int k = i >> 6, c = i & 63;
        float4 v = (c < 32) ? *(const float4*)&W2l[k * OUT_C + c]
                            : *(const float4*)&W2r[k * OUT_C + (c - 32)];
        *(float4*)&sW2[i] = v;
    }
    if (tid < HID_C) sB[tid] = b1[tid];

    // Stage inputs transposed [k][node], agg pre-scaled by 1/max(deg,1)
    int nodeBase = blockIdx.x * NT;
    for (int i = tid; i < NT * 8; i += 256) {       // 1024 float4 slots, 4 iters
        int node = i >> 3, kc = i & 7;
        int ng = nodeBase + node;
        float4 a = {0,0,0,0}, xv = {0,0,0,0};
        float inv = 0.0f;
        if (ng < n_nodes) {
            inv = 1.0f / fmaxf(cnt[ng], 1.0f);
            a  = *(const float4*)(agg + (long long)ng * IN_C + kc * 4);
            xv = *(const float4*)(x   + (long long)ng * IN_C + kc * 4);
        }
        int kb = kc * 4;
        sAgg[(kb + 0) * STRIDE + node] = a.x * inv;
        sAgg[(kb + 1) * STRIDE + node] = a.y * inv;
        sAgg[(kb + 2) * STRIDE + node] = a.z * inv;
        sAgg[(kb + 3) * STRIDE + node] = a.w * inv;
        sX  [(kb + 0) * STRIDE + node] = xv.x;
        sX  [(kb + 1) * STRIDE + node] = xv.y;
        sX  [(kb + 2) * STRIDE + node] = xv.z;
        sX  [(kb + 3) * STRIDE + node] = xv.w;
    }
    __syncthreads();

    const int cb = warp * 8;   // this warp's channel base
    const int nb = lane * 4;   // this lane's node base (within block)

    // GEMM1: acc[n][p] = h channels (cb+2p, cb+2p+1) for node nb+n
    unsigned long long acc[4][4];
#pragma unroll
    for (int n = 0; n < 4; n++)
#pragma unroll
        for (int p = 0; p < 4; p++) acc[n][p] = 0ull;

#pragma unroll
    for (int k = 0; k < IN_C; k++) {
        float4 av = *(const float4*)&sAgg[k * STRIDE + nb];
        float4 xv = *(const float4*)&sX  [k * STRIDE + nb];
        ulonglong2 wl0 = *(const ulonglong2*)&sW1l[k * HID_C + cb];
        ulonglong2 wl1 = *(const ulonglong2*)&sW1l[k * HID_C + cb + 4];
        ulonglong2 wr0 = *(const ulonglong2*)&sW1r[k * HID_C + cb];
        ulonglong2 wr1 = *(const ulonglong2*)&sW1r[k * HID_C + cb + 4];
        float avf[4] = {av.x, av.y, av.z, av.w};
        float xvf[4] = {xv.x, xv.y, xv.z, xv.w};
#pragma unroll
        for (int n = 0; n < 4; n++) {
            unsigned long long a2 = pack2(avf[n]);
            fma2(acc[n][0], a2, wl0.x); fma2(acc[n][1], a2, wl0.y);
            fma2(acc[n][2], a2, wl1.x); fma2(acc[n][3], a2, wl1.y);
            unsigned long long x2 = pack2(xvf[n]);
            fma2(acc[n][0], x2, wr0.x); fma2(acc[n][1], x2, wr0.y);
            fma2(acc[n][2], x2, wr1.x); fma2(acc[n][3], x2, wr1.y);
        }
    }
    __syncthreads();   // all sAgg/sX reads done before sH overlay write

    // bias + relu -> sH[ch][node], one STS.128 (4 nodes) per channel
#pragma unroll
    for (int c = 0; c < 8; c += 2) {
        float2 p0 = unpack2(acc[0][c / 2]);
        float2 p1 = unpack2(acc[1][c / 2]);
        float2 p2 = unpack2(acc[2][c / 2]);
        float2 p3 = unpack2(acc[3][c / 2]);
        float b0 = sB[cb + c], b1v = sB[cb + c + 1];
        float4 v0 = {fmaxf(p0.x + b0, 0.f), fmaxf(p1.x + b0, 0.f),
                     fmaxf(p2.x + b0, 0.f), fmaxf(p3.x + b0, 0.f)};
        float4 v1 = {fmaxf(p0.y + b1v, 0.f), fmaxf(p1.y + b1v, 0.f),
                     fmaxf(p2.y + b1v, 0.f), fmaxf(p3.y + b1v, 0.f)};
        *(float4*)&sH[(cb + c)     * STRIDE + nb] = v0;
        *(float4*)&sH[(cb + c + 1) * STRIDE + nb] = v1;
    }
    __syncthreads();

    // GEMM2: [hw|hr] = h @ sW2 (k=64)
    unsigned long long acc2[4][4];
#pragma unroll
    for (int n = 0; n < 4; n++)
#pragma unroll
        for (int p = 0; p < 4; p++) acc2[n][p] = 0ull;

#pragma unroll 8
    for (int k = 0; k < HID_C; k++) {
        float4 hv = *(const float4*)&sH[k * STRIDE + nb];
        ulonglong2 w0 = *(const ulonglong2*)&sW2[k * 64 + cb];
        ulonglong2 w1 = *(const ulonglong2*)&sW2[k * 64 + cb + 4];
        float hvf[4] = {hv.x, hv.y, hv.z, hv.w};
#pragma unroll
        for (int n = 0; n < 4; n++) {
            unsigned long long h2 = pack2(hvf[n]);
            fma2(acc2[n][0], h2, w0.x); fma2(acc2[n][1], h2, w0.y);
            fma2(acc2[n][2], h2, w1.x); fma2(acc2[n][3], h2, w1.y);
        }
    }

    // Epilogue: warp's 8 channels land in hw (cb<32) or hr (cb>=32)
    float* basep = (cb < 32) ? hw : hr;
    int coff = (cb < 32) ? cb : cb - 32;
#pragma unroll
    for (int n = 0; n < 4; n++) {
        int node = nodeBase + nb + n;
        if (node < n_nodes) {
            float2 q0 = unpack2(acc2[n][0]);
            float2 q1 = unpack2(acc2[n][1]);
            float2 q2 = unpack2(acc2[n][2]);
            float2 q3 = unpack2(acc2[n][3]);
            float4 o0 = {q0.x, q0.y, q1.x, q1.y};
            float4 o1 = {q2.x, q2.y, q3.x, q3.y};
            *(float4*)(basep + (long long)node * OUT_C + coff)     = o0;
            *(float4*)(basep + (long long)node * OUT_C + coff + 4) = o1;
        }
    }
}

// ---------------------------------------------------------------------------
// Final elementwise: out[n,c] = agg2[n,c]/max(cnt[n],1) + b2[c] + hr[n,c]
// ---------------------------------------------------------------------------
__global__ __launch_bounds__(256)
void final_add(const float* __restrict__ agg,
               const float* __restrict__ cnt,
               const float* __restrict__ b,
               const float* __restrict__ hr,
               float* __restrict__ out,
               int n_nodes)
{
    __shared__ float sB[OUT_C];
    if (threadIdx.x < OUT_C) sB[threadIdx.x] = b[threadIdx.x];
    __syncthreads();

    int t = blockIdx.x * 256 + threadIdx.x;
    int total = n_nodes * (OUT_C / 4);
    if (t >= total) return;

    int node = t >> 3;
    int seg  = t & 7;

    float inv = 1.0f / fmaxf(cnt[node], 1.0f);
    float4 a = *(const float4*)(agg + (long long)node * OUT_C + seg * 4);
    float4 r = *(const float4*)(hr  + (long long)node * OUT_C + seg * 4);
    float4 o;
    o.x = a.x * inv + sB[seg * 4 + 0] + r.x;
    o.y = a.y * inv + sB[seg * 4 + 1] + r.y;
    o.z = a.z * inv + sB[seg * 4 + 2] + r.z;
    o.w = a.w * inv + sB[seg * 4 + 3] + r.w;
    *(float4*)(out + (long long)node * OUT_C + seg * 4) = o;
}

// ---------------------------------------------------------------------------
// Launch
// ---------------------------------------------------------------------------
extern "C" void kernel_launch(void* const* d_in, const int* in_sizes, int n_in,
                              void* d_out, int out_size)
{
    const float* x    = (const float*)d_in[0];
    const int*   ei   = (const int*)d_in[1];
    const float* W1l  = (const float*)d_in[2];
    const float* b1   = (const float*)d_in[3];
    const float* W1r  = (const float*)d_in[4];
    const float* W2l  = (const float*)d_in[5];
    const float* b2   = (const float*)d_in[6];
    const float* W2r  = (const float*)d_in[7];
    float*       out  = (float*)d_out;

    const int n_nodes = in_sizes[0] / IN_C;
    const int n_edges = in_sizes[1] / 2;

    float *agg1, *hw, *hr, *agg2, *cnt;
    cudaGetSymbolAddress((void**)&agg1, g_agg1);
    cudaGetSymbolAddress((void**)&hw,   g_hw);
    cudaGetSymbolAddress((void**)&hr,   g_hr);
    cudaGetSymbolAddress((void**)&agg2, g_agg2);
    cudaGetSymbolAddress((void**)&cnt,  g_cnt);

    cudaMemsetAsync(agg1, 0, (size_t)n_nodes * IN_C  * sizeof(float));
    cudaMemsetAsync(agg2, 0, (size_t)n_nodes * OUT_C * sizeof(float));
    cudaMemsetAsync(cnt,  0, (size_t)n_nodes * sizeof(float));

    const int warps  = (n_edges + 31) / 32;
    const int blocks_sc = (warps * 32 + 255) / 256;

    // Layer 1 aggregate (32-dim) + degree count
    scatter32<true><<<blocks_sc, 256>>>(x, ei, agg1, cnt, n_edges);

    // Tiled fused transform -> hw, hr
    {
        const int smem_bytes = (HID_C * STRIDE + 2 * IN_C * HID_C
                              + HID_C * 64 + HID_C) * (int)sizeof(float);
        static bool attr_set = false;
        if (!attr_set) {
            cudaFuncSetAttribute(transform_l1_tiled,
                                 cudaFuncAttributeMaxDynamicSharedMemorySize,
                                 smem_bytes);
            attr_set = true;
        }
        int blocks = (n_nodes + NT - 1) / NT;
        transform_l1_tiled<<<blocks, 256, smem_bytes>>>(
            x, agg1, cnt, W1l, b1, W1r, W2l, W2r, hw, hr, n_nodes);
    }

    // Layer 2 aggregate (32-dim)
    scatter32<false><<<blocks_sc, 256>>>(hw, ei, agg2, nullptr, n_edges);

    // Final elementwise combine
    {
        int total = n_nodes * (OUT_C / 4);
        int blocks = (total + 255) / 256;
        final_add<<<blocks, 256>>>(agg2, cnt, b2, hr, out, n_nodes);
    }
}

// round 12
// speedup vs baseline: 1.7961x; 1.0442x over previous
#include <cuda_runtime.h>
#include <cstdint>

#define MAX_NODES 100000
#define IN_C  32
#define HID_C 64
#define OUT_C 32
#define NT 128          // nodes per transform block
#define STRIDE 132      // padded shared row stride (floats)

// Scratch (__device__ globals: allocation-free rule)
__device__ __align__(16) float g_agg1  [MAX_NODES * IN_C];   // 12.8 MB
__device__ __align__(16) float g_hw    [MAX_NODES * OUT_C];  // relu(h) @ W2_l
__device__               float g_cnt   [MAX_NODES];
__device__               float g_invcnt[MAX_NODES];

// ---------------------------------------------------------------------------
// Packed f32x2 helpers (Blackwell FFMA2)
// ---------------------------------------------------------------------------
__device__ __forceinline__ void fma2(unsigned long long& d,
                                     unsigned long long a,
                                     unsigned long long b)
{
    asm("fma.rn.f32x2 %0, %1, %2, %0;" : "+l"(d) : "l"(a), "l"(b));
}
__device__ __forceinline__ unsigned long long pack2(float v)
{
    unsigned long long r;
    asm("mov.b64 %0, {%1, %1};" : "=l"(r) : "r"(__float_as_uint(v)));
    return r;
}
__device__ __forceinline__ float2 unpack2(unsigned long long v)
{
    float2 f;
    asm("mov.b64 {%0, %1}, %2;" : "=f"(f.x), "=f"(f.y) : "l"(v));
    return f;
}

// ---------------------------------------------------------------------------
// Warp-shuffle scatter-add, C=32, layer 1: agg1 += x[src]; cnt[dst]++.
// ---------------------------------------------------------------------------
__global__ void scatter32(const float* __restrict__ feat,
                          const int* __restrict__ ei,
                          float* __restrict__ agg,
                          float* __restrict__ cnt,
                          int n_edges)
{
    int warp = (blockIdx.x * blockDim.x + threadIdx.x) >> 5;
    int lane = threadIdx.x & 31;
    int base = warp * 32;
    if (base >= n_edges) return;

    int my_e   = base + lane;
    bool has   = my_e < n_edges;
    int e_clmp = has ? my_e : (n_edges - 1);
    int my_src = __ldg(ei + e_clmp);
    int my_dst = __ldg(ei + n_edges + e_clmp);

    if (has) atomicAdd(&cnt[my_dst], 1.0f);

    int seg = lane & 7;
    int sub = lane >> 3;

#pragma unroll
    for (int pass = 0; pass < 8; pass++) {
        int eslot = pass * 4 + sub;
        int src = __shfl_sync(0xffffffffu, my_src, eslot);
        int dst = __shfl_sync(0xffffffffu, my_dst, eslot);
        if (base + eslot < n_edges) {
            float4 v = *(const float4*)(feat + (long long)src * 32 + seg * 4);
            atomicAdd((float4*)(agg + (long long)dst * 32 + seg * 4), v);
        }
    }
}

// ---------------------------------------------------------------------------
// Layer-2 scatter, pre-scaled: out[dst] += hw[src] * invcnt[dst].
// out was pre-initialized by the transform with b2 + hr. No tail kernel.
// ---------------------------------------------------------------------------
__global__ void scatter32_scaled(const float* __restrict__ feat,
                                 const int* __restrict__ ei,
                                 const float* __restrict__ invcnt,
                                 float* __restrict__ outp,
                                 int n_edges)
{
    int warp = (blockIdx.x * blockDim.x + threadIdx.x) >> 5;
    int lane = threadIdx.x & 31;
    int base = warp * 32;
    if (base >= n_edges) return;

    int my_e   = base + lane;
    bool has   = my_e < n_edges;
    int e_clmp = has ? my_e : (n_edges - 1);
    int my_src = __ldg(ei + e_clmp);
    int my_dst = __ldg(ei + n_edges + e_clmp);
    float my_inv = __ldg(invcnt + my_dst);

    int seg = lane & 7;
    int sub = lane >> 3;

#pragma unroll
    for (int pass = 0; pass < 8; pass++) {
        int eslot = pass * 4 + sub;
        int src   = __shfl_sync(0xffffffffu, my_src, eslot);
        int dst   = __shfl_sync(0xffffffffu, my_dst, eslot);
        float inv = __shfl_sync(0xffffffffu, my_inv, eslot);
        if (base + eslot < n_edges) {
            float4 v = *(const float4*)(feat + (long long)src * 32 + seg * 4);
            v.x *= inv; v.y *= inv; v.z *= inv; v.w *= inv;
            atomicAdd((float4*)(outp + (long long)dst * 32 + seg * 4), v);
        }
    }
}

// ---------------------------------------------------------------------------
// Tiled fused transform. Block = 128 nodes, 256 threads.
//   GEMM1: h = relu( (agg1/deg) @ W1l + b1 + x @ W1r )   (h -> shared only)
//   GEMM2: [hw | out_init] = h @ [W2l | W2r],  out_init += b2
// Also writes invcnt[node] = 1/max(cnt,1) for scatter2's pre-scaling.
// ---------------------------------------------------------------------------
__global__ __launch_bounds__(256)
void transform_l1_tiled(const float* __restrict__ x,
                        const float* __restrict__ agg,
                        const float* __restrict__ cnt,
                        const float* __restrict__ W1l,
                        const float* __restrict__ b1,
                        const float* __restrict__ W1r,
                        const float* __restrict__ W2l,
                        const float* __restrict__ b2,
                        const float* __restrict__ W2r,
                        float* __restrict__ hw,
                        float* __restrict__ outp,
                        float* __restrict__ invcnt,
                        int n_nodes)
{
    extern __shared__ __align__(16) float smem[];
    float* sAgg = smem;                          // [32][STRIDE]
    float* sX   = smem + IN_C * STRIDE;          // [32][STRIDE]
    float* sH   = smem;                          // [64][STRIDE] (overlay)
    float* sW1l = smem + HID_C * STRIDE;
    float* sW1r = sW1l + IN_C * HID_C;
    float* sW2  = sW1r + IN_C * HID_C;           // 64*64 = [W2l | W2r]
    float* sB   = sW2  + HID_C * 64;             // 64 (b1)
    float* sB2  = sB   + HID_C;                  // 32 (b2)

    int tid  = threadIdx.x;
    int warp = tid >> 5;
    int lane = tid & 31;

    for (int i = tid * 4; i < IN_C * HID_C; i += 256 * 4) {
        *(float4*)&sW1l[i] = *(const float4*)&W1l[i];
        *(float4*)&sW1r[i] = *(const float4*)&W1r[i];
    }
    for (int i = tid * 4; i < HID_C * 64; i += 256 * 4) {
        int k = i >> 6, c = i & 63;
        float4 v = (c < 32) ? *(const float4*)&W2l[k * OUT_C + c]
                            : *(const float4*)&W2r[k * OUT_C + (c - 32)];
        *(float4*)&sW2[i] = v;
    }
    if (tid < HID_C) sB[tid] = b1[tid];
    if (tid < OUT_C) sB2[tid] = b2[tid];

    // Stage inputs transposed [k][node], agg pre-scaled by 1/max(deg,1)
    int nodeBase = blockIdx.x * NT;
    for (int i = tid; i < NT * 8; i += 256) {
        int node = i >> 3, kc = i & 7;
        int ng = nodeBase + node;
        float4 a = {0,0,0,0}, xv = {0,0,0,0};
        float inv = 0.0f;
        if (ng < n_nodes) {
            inv = 1.0f / fmaxf(cnt[ng], 1.0f);
            a  = *(const float4*)(agg + (long long)ng * IN_C + kc * 4);
            xv = *(const float4*)(x   + (long long)ng * IN_C + kc * 4);
            if (kc == 0) invcnt[ng] = inv;   // free side-product
        }
        int kb = kc * 4;
        sAgg[(kb + 0) * STRIDE + node] = a.x * inv;
        sAgg[(kb + 1) * STRIDE + node] = a.y * inv;
        sAgg[(kb + 2) * STRIDE + node] = a.z * inv;
        sAgg[(kb + 3) * STRIDE + node] = a.w * inv;
        sX  [(kb + 0) * STRIDE + node] = xv.x;
        sX  [(kb + 1) * STRIDE + node] = xv.y;
        sX  [(kb + 2) * STRIDE + node] = xv.z;
        sX  [(kb + 3) * STRIDE + node] = xv.w;
    }
    __syncthreads();

    const int cb = warp * 8;   // this warp's channel base
    const int nb = lane * 4;   // this lane's node base

    unsigned long long acc[4][4];
#pragma unroll
    for (int n = 0; n < 4; n++)
#pragma unroll
        for (int p = 0; p < 4; p++) acc[n][p] = 0ull;

#pragma unroll
    for (int k = 0; k < IN_C; k++) {
        float4 av = *(const float4*)&sAgg[k * STRIDE + nb];
        float4 xv = *(const float4*)&sX  [k * STRIDE + nb];
        ulonglong2 wl0 = *(const ulonglong2*)&sW1l[k * HID_C + cb];
        ulonglong2 wl1 = *(const ulonglong2*)&sW1l[k * HID_C + cb + 4];
        ulonglong2 wr0 = *(const ulonglong2*)&sW1r[k * HID_C + cb];
        ulonglong2 wr1 = *(const ulonglong2*)&sW1r[k * HID_C + cb + 4];
        float avf[4] = {av.x, av.y, av.z, av.w};
        float xvf[4] = {xv.x, xv.y, xv.z, xv.w};
#pragma unroll
        for (int n = 0; n < 4; n++) {
            unsigned long long a2 = pack2(avf[n]);
            fma2(acc[n][0], a2, wl0.x); fma2(acc[n][1], a2, wl0.y);
            fma2(acc[n][2], a2, wl1.x); fma2(acc[n][3], a2, wl1.y);
            unsigned long long x2 = pack2(xvf[n]);
            fma2(acc[n][0], x2, wr0.x); fma2(acc[n][1], x2, wr0.y);
            fma2(acc[n][2], x2, wr1.x); fma2(acc[n][3], x2, wr1.y);
        }
    }
    __syncthreads();

    // bias + relu -> sH[ch][node]
#pragma unroll
    for (int c = 0; c < 8; c += 2) {
        float2 p0 = unpack2(acc[0][c / 2]);
        float2 p1 = unpack2(acc[1][c / 2]);
        float2 p2 = unpack2(acc[2][c / 2]);
        float2 p3 = unpack2(acc[3][c / 2]);
        float b0 = sB[cb + c], b1v = sB[cb + c + 1];
        float4 v0 = {fmaxf(p0.x + b0, 0.f), fmaxf(p1.x + b0, 0.f),
                     fmaxf(p2.x + b0, 0.f), fmaxf(p3.x + b0, 0.f)};
        float4 v1 = {fmaxf(p0.y + b1v, 0.f), fmaxf(p1.y + b1v, 0.f),
                     fmaxf(p2.y + b1v, 0.f), fmaxf(p3.y + b1v, 0.f)};
        *(float4*)&sH[(cb + c)     * STRIDE + nb] = v0;
        *(float4*)&sH[(cb + c + 1) * STRIDE + nb] = v1;
    }
    __syncthreads();

    // GEMM2: [hw | out_init] = h @ sW2 (k=64)
    unsigned long long acc2[4][4];
#pragma unroll
    for (int n = 0; n < 4; n++)
#pragma unroll
        for (int p = 0; p < 4; p++) acc2[n][p] = 0ull;

#pragma unroll 8
    for (int k = 0; k < HID_C; k++) {
        float4 hv = *(const float4*)&sH[k * STRIDE + nb];
        ulonglong2 w0 = *(const ulonglong2*)&sW2[k * 64 + cb];
        ulonglong2 w1 = *(const ulonglong2*)&sW2[k * 64 + cb + 4];
        float hvf[4] = {hv.x, hv.y, hv.z, hv.w};
#pragma unroll
        for (int n = 0; n < 4; n++) {
            unsigned long long h2 = pack2(hvf[n]);
            fma2(acc2[n][0], h2, w0.x); fma2(acc2[n][1], h2, w0.y);
            fma2(acc2[n][2], h2, w1.x); fma2(acc2[n][3], h2, w1.y);
        }
    }

    // Epilogue: cb<32 -> hw ; cb>=32 -> out = value + b2 (scatter2 adds onto it)
    bool to_out = (cb >= 32);
    float* basep = to_out ? outp : hw;
    int coff = to_out ? cb - 32 : cb;
    float add0 = to_out ? sB2[coff + 0] : 0.f;
    float add1 = to_out ? sB2[coff + 1] : 0.f;
    float add2 = to_out ? sB2[coff + 2] : 0.f;
    float add3 = to_out ? sB2[coff + 3] : 0.f;
    float add4 = to_out ? sB2[coff + 4] : 0.f;
    float add5 = to_out ? sB2[coff + 5] : 0.f;
    float add6 = to_out ? sB2[coff + 6] : 0.f;
    float add7 = to_out ? sB2[coff + 7] : 0.f;
#pragma unroll
    for (int n = 0; n < 4; n++) {
        int node = nodeBase + nb + n;
        if (node < n_nodes) {
            float2 q0 = unpack2(acc2[n][0]);
            float2 q1 = unpack2(acc2[n][1]);
            float2 q2 = unpack2(acc2[n][2]);
            float2 q3 = unpack2(acc2[n][3]);
            float4 o0 = {q0.x + add0, q0.y + add1, q1.x + add2, q1.y + add3};
            float4 o1 = {q2.x + add4, q2.y + add5, q3.x + add6, q3.y + add7};
            *(float4*)(basep + (long long)node * OUT_C + coff)     = o0;
            *(float4*)(basep + (long long)node * OUT_C + coff + 4) = o1;
        }
    }
}

// ---------------------------------------------------------------------------
// Launch
// ---------------------------------------------------------------------------
extern "C" void kernel_launch(void* const* d_in, const int* in_sizes, int n_in,
                              void* d_out, int out_size)
{
    const float* x    = (const float*)d_in[0];
    const int*   ei   = (const int*)d_in[1];
    const float* W1l  = (const float*)d_in[2];
    const float* b1   = (const float*)d_in[3];
    const float* W1r  = (const float*)d_in[4];
    const float* W2l  = (const float*)d_in[5];
    const float* b2   = (const float*)d_in[6];
    const float* W2r  = (const float*)d_in[7];
    float*       out  = (float*)d_out;

    const int n_nodes = in_sizes[0] / IN_C;
    const int n_edges = in_sizes[1] / 2;

    float *agg1, *hw, *cnt, *invcnt;
    cudaGetSymbolAddress((void**)&agg1,   g_agg1);
    cudaGetSymbolAddress((void**)&hw,     g_hw);
    cudaGetSymbolAddress((void**)&cnt,    g_cnt);
    cudaGetSymbolAddress((void**)&invcnt, g_invcnt);

    cudaMemsetAsync(agg1, 0, (size_t)n_nodes * IN_C * sizeof(float));
    cudaMemsetAsync(cnt,  0, (size_t)n_nodes * sizeof(float));

    const int warps  = (n_edges + 31) / 32;
    const int blocks_sc = (warps * 32 + 255) / 256;

    // Layer 1 aggregate + degree count
    scatter32<<<blocks_sc, 256>>>(x, ei, agg1, cnt, n_edges);

    // Tiled fused transform -> hw, out(=b2+hr), invcnt
    {
        const int smem_bytes = (HID_C * STRIDE + 2 * IN_C * HID_C
                              + HID_C * 64 + HID_C + OUT_C) * (int)sizeof(float);
        static bool attr_set = false;
        if (!attr_set) {
            cudaFuncSetAttribute(transform_l1_tiled,
                                 cudaFuncAttributeMaxDynamicSharedMemorySize,
                                 smem_bytes);
            attr_set = true;
        }
        int blocks = (n_nodes + NT - 1) / NT;
        transform_l1_tiled<<<blocks, 256, smem_bytes>>>(
            x, agg1, cnt, W1l, b1, W1r, W2l, b2, W2r, hw, out, invcnt, n_nodes);
    }

    // Layer 2 aggregate, pre-scaled, directly into out (no tail kernel)
    scatter32_scaled<<<blocks_sc, 256>>>(hw, ei, invcnt, out, n_edges);
}

// round 13
// speedup vs baseline: 1.7995x; 1.0019x over previous
#include <cuda_runtime.h>
#include <cstdint>

#define MAX_NODES 100000
#define MAX_EDGES 1600000
#define IN_C  32
#define HID_C 64
#define OUT_C 32
#define NT 128          // nodes per transform block
#define STRIDE 132      // padded shared row stride (floats)
#define SCAN_CHUNK 1024
#define MAX_CHUNKS 128

// Scratch (__device__ globals: allocation-free rule)
__device__ __align__(16) float g_agg1[MAX_NODES * IN_C];   // raw sums
__device__ __align__(16) float g_hw  [MAX_NODES * OUT_C];  // relu(h) @ W2_l
__device__ int g_deg   [MAX_NODES];
__device__ int g_rowptr[MAX_NODES + 1];
__device__ int g_cursor[MAX_NODES];
__device__ int g_col   [MAX_EDGES];
__device__ int g_chunkSum[MAX_CHUNKS];

// ---------------------------------------------------------------------------
// Packed f32x2 helpers (Blackwell FFMA2)
// ---------------------------------------------------------------------------
__device__ __forceinline__ void fma2(unsigned long long& d,
                                     unsigned long long a,
                                     unsigned long long b)
{
    asm("fma.rn.f32x2 %0, %1, %2, %0;" : "+l"(d) : "l"(a), "l"(b));
}
__device__ __forceinline__ unsigned long long pack2(float v)
{
    unsigned long long r;
    asm("mov.b64 %0, {%1, %1};" : "=l"(r) : "r"(__float_as_uint(v)));
    return r;
}
__device__ __forceinline__ float2 unpack2(unsigned long long v)
{
    float2 f;
    asm("mov.b64 {%0, %1}, %2;" : "=f"(f.x), "=f"(f.y) : "l"(v));
    return f;
}

// ---------------------------------------------------------------------------
// CSR build (scalar atomics — R8 lesson: batched dependent atomics serialize)
// ---------------------------------------------------------------------------
__global__ void deg_count(const int* __restrict__ dst, int* __restrict__ deg,
                          int n_edges)
{
    int e = blockIdx.x * blockDim.x + threadIdx.x;
    if (e < n_edges) atomicAdd(&deg[dst[e]], 1);
}

__global__ void scan1(const int* __restrict__ deg, int* __restrict__ pref,
                      int* __restrict__ chunkSum, int n)
{
    __shared__ int sT[256];
    int chunk = blockIdx.x;
    int base  = chunk * SCAN_CHUNK;
    int t     = threadIdx.x;

    int v[4], s = 0;
#pragma unroll
    for (int j = 0; j < 4; j++) {
        int idx = base + t * 4 + j;
        v[j] = (idx < n) ? deg[idx] : 0;
        s += v[j];
    }
    sT[t] = s;
    __syncthreads();
#pragma unroll
    for (int off = 1; off < 256; off <<= 1) {
        int y = (t >= off) ? sT[t - off] : 0;
        __syncthreads();
        sT[t] += y;
        __syncthreads();
    }
    int excl = sT[t] - s;
#pragma unroll
    for (int j = 0; j < 4; j++) {
        int idx = base + t * 4 + j;
        if (idx < n) pref[idx] = excl;
        excl += v[j];
    }
    if (t == 255) chunkSum[chunk] = sT[255];
}

__global__ void scan2b(int* __restrict__ rowptr, int* __restrict__ cursor,
                       const int* __restrict__ chunkSum, int n, int nchunks)
{
    __shared__ int sCS[MAX_CHUNKS];
    for (int j = threadIdx.x; j < nchunks; j += blockDim.x)
        sCS[j] = chunkSum[j];
    __syncthreads();

    int i = blockIdx.x * blockDim.x + threadIdx.x;
    if (i < n) {
        int myChunk = i / SCAN_CHUNK;
        int off = 0;
        for (int j = 0; j < myChunk; j++) off += sCS[j];
        int v = rowptr[i] + off;
        rowptr[i] = v;
        cursor[i] = v;
    }
    if (i == 0) {
        int tot = 0;
        for (int j = 0; j < nchunks; j++) tot += sCS[j];
        rowptr[n] = tot;
    }
}

__global__ void csr_fill(const int* __restrict__ src, const int* __restrict__ dst,
                         int* __restrict__ cursor, int* __restrict__ col,
                         int n_edges)
{
    int e = blockIdx.x * blockDim.x + threadIdx.x;
    if (e >= n_edges) return;
    int d = dst[e];
    int pos = atomicAdd(&cursor[d], 1);
    col[pos] = src[e];
}

// ---------------------------------------------------------------------------
// CSR gather, C=32: one warp per node; 8 edges/iter (2 independent load
// rounds for MLP); cross-lane shfl reduce; plain stores, no atomics.
//   FUSE_OUT=false: outp[n,:] = raw sum
//   FUSE_OUT=true : outp[n,:] = sum/max(deg,1) + outp[n,:]   (out pre-init b2+hr)
// ---------------------------------------------------------------------------
template <bool FUSE_OUT>
__global__ __launch_bounds__(256)
void gather32(const float* __restrict__ feat,
              const int* __restrict__ rowptr,
              const int* __restrict__ col,
              float* __restrict__ outp,
              int n_nodes)
{
    int node = (blockIdx.x * blockDim.x + threadIdx.x) >> 5;
    int lane = threadIdx.x & 31;
    if (node >= n_nodes) return;

    int beg = rowptr[node];
    int end = rowptr[node + 1];

    int sub = lane >> 3;   // 0..3
    int seg = lane & 7;    // float4 segment

    float4 acc = {0.f, 0.f, 0.f, 0.f};
    for (int i = beg; i < end; i += 8) {
        int cv = (lane < 8 && i + lane < end) ? __ldg(col + i + lane) : 0;
        int c0 = __shfl_sync(0xffffffffu, cv, sub);
        int c1 = __shfl_sync(0xffffffffu, cv, 4 + sub);
        bool p0 = (i + sub) < end;
        bool p1 = (i + 4 + sub) < end;
        float4 v0 = {0,0,0,0}, v1 = {0,0,0,0};
        if (p0) v0 = *(const float4*)(feat + (long long)c0 * 32 + seg * 4);
        if (p1) v1 = *(const float4*)(feat + (long long)c1 * 32 + seg * 4);
        acc.x += v0.x + v1.x; acc.y += v0.y + v1.y;
        acc.z += v0.z + v1.z; acc.w += v0.w + v1.w;
    }
#pragma unroll
    for (int off = 8; off < 32; off <<= 1) {
        acc.x += __shfl_xor_sync(0xffffffffu, acc.x, off);
        acc.y += __shfl_xor_sync(0xffffffffu, acc.y, off);
        acc.z += __shfl_xor_sync(0xffffffffu, acc.z, off);
        acc.w += __shfl_xor_sync(0xffffffffu, acc.w, off);
    }
    if (lane < 8) {
        float* dstp = outp + (long long)node * 32 + seg * 4;
        if (FUSE_OUT) {
            float inv = 1.0f / fmaxf((float)(end - beg), 1.0f);
            float4 prev = *(const float4*)dstp;
            float4 o;
            o.x = acc.x * inv + prev.x;
            o.y = acc.y * inv + prev.y;
            o.z = acc.z * inv + prev.z;
            o.w = acc.w * inv + prev.w;
            *(float4*)dstp = o;
        } else {
            *(float4*)dstp = acc;
        }
    }
}

// ---------------------------------------------------------------------------
// Tiled fused transform (R11 structure). Block = 128 nodes, 256 threads.
//   GEMM1: h = relu( (agg1/deg) @ W1l + b1 + x @ W1r )   (h -> shared only)
//   GEMM2: [hw | out_init] = h @ [W2l | W2r],  out_init += b2
// deg comes from rowptr (CSR); no float cnt anywhere.
// ---------------------------------------------------------------------------
__global__ __launch_bounds__(256)
void transform_l1_tiled(const float* __restrict__ x,
                        const float* __restrict__ agg,
                        const int* __restrict__ rowptr,
                        const float* __restrict__ W1l,
                        const float* __restrict__ b1,
                        const float* __restrict__ W1r,
                        const float* __restrict__ W2l,
                        const float* __restrict__ b2,
                        const float* __restrict__ W2r,
                        float* __restrict__ hw,
                        float* __restrict__ outp,
                        int n_nodes)
{
    extern __shared__ __align__(16) float smem[];
    float* sAgg = smem;                          // [32][STRIDE]
    float* sX   = smem + IN_C * STRIDE;          // [32][STRIDE]
    float* sH   = smem;                          // [64][STRIDE] (overlay)
    float* sW1l = smem + HID_C * STRIDE;
    float* sW1r = sW1l + IN_C * HID_C;
    float* sW2  = sW1r + IN_C * HID_C;           // 64*64 = [W2l | W2r]
    float* sB   = sW2  + HID_C * 64;             // 64 (b1)
    float* sB2  = sB   + HID_C;                  // 32 (b2)

    int tid  = threadIdx.x;
    int warp = tid >> 5;
    int lane = tid & 31;

    for (int i = tid * 4; i < IN_C * HID_C; i += 256 * 4) {
        *(float4*)&sW1l[i] = *(const float4*)&W1l[i];
        *(float4*)&sW1r[i] = *(const float4*)&W1r[i];
    }
    for (int i = tid * 4; i < HID_C * 64; i += 256 * 4) {
        int k = i >> 6, c = i & 63;
        float4 v = (c < 32) ? *(const float4*)&W2l[k * OUT_C + c]
                            : *(const float4*)&W2r[k * OUT_C + (c - 32)];
        *(float4*)&sW2[i] = v;
    }
    if (tid < HID_C) sB[tid] = b1[tid];
    if (tid < OUT_C) sB2[tid] = b2[tid];

    // Stage inputs transposed [k][node], agg pre-scaled by 1/max(deg,1)
    int nodeBase = blockIdx.x * NT;
    for (int i = tid; i < NT * 8; i += 256) {
        int node = i >> 3, kc = i & 7;
        int ng = nodeBase + node;
        float4 a = {0,0,0,0}, xv = {0,0,0,0};
        float inv = 0.0f;
        if (ng < n_nodes) {
            int deg = rowptr[ng + 1] - rowptr[ng];
            inv = 1.0f / fmaxf((float)deg, 1.0f);
            a  = *(const float4*)(agg + (long long)ng * IN_C + kc * 4);
            xv = *(const float4*)(x   + (long long)ng * IN_C + kc * 4);
        }
        int kb = kc * 4;
        sAgg[(kb + 0) * STRIDE + node] = a.x * inv;
        sAgg[(kb + 1) * STRIDE + node] = a.y * inv;
        sAgg[(kb + 2) * STRIDE + node] = a.z * inv;
        sAgg[(kb + 3) * STRIDE + node] = a.w * inv;
        sX  [(kb + 0) * STRIDE + node] = xv.x;
        sX  [(kb + 1) * STRIDE + node] = xv.y;
        sX  [(kb + 2) * STRIDE + node] = xv.z;
        sX  [(kb + 3) * STRIDE + node] = xv.w;
    }
    __syncthreads();

    const int cb = warp * 8;
    const int nb = lane * 4;

    unsigned long long acc[4][4];
#pragma unroll
    for (int n = 0; n < 4; n++)
#pragma unroll
        for (int p = 0; p < 4; p++) acc[n][p] = 0ull;

#pragma unroll
    for (int k = 0; k < IN_C; k++) {
        float4 av = *(const float4*)&sAgg[k * STRIDE + nb];
        float4 xv = *(const float4*)&sX  [k * STRIDE + nb];
        ulonglong2 wl0 = *(const ulonglong2*)&sW1l[k * HID_C + cb];
        ulonglong2 wl1 = *(const ulonglong2*)&sW1l[k * HID_C + cb + 4];
        ulonglong2 wr0 = *(const ulonglong2*)&sW1r[k * HID_C + cb];
        ulonglong2 wr1 = *(const ulonglong2*)&sW1r[k * HID_C + cb + 4];
        float avf[4] = {av.x, av.y, av.z, av.w};
        float xvf[4] = {xv.x, xv.y, xv.z, xv.w};
#pragma unroll
        for (int n = 0; n < 4; n++) {
            unsigned long long a2 = pack2(avf[n]);
            fma2(acc[n][0], a2, wl0.x); fma2(acc[n][1], a2, wl0.y);
            fma2(acc[n][2], a2, wl1.x); fma2(acc[n][3], a2, wl1.y);
            unsigned long long x2 = pack2(xvf[n]);
            fma2(acc[n][0], x2, wr0.x); fma2(acc[n][1], x2, wr0.y);
            fma2(acc[n][2], x2, wr1.x); fma2(acc[n][3], x2, wr1.y);
        }
    }
    __syncthreads();

    // bias + relu -> sH[ch][node]
#pragma unroll
    for (int c = 0; c < 8; c += 2) {
        float2 p0 = unpack2(acc[0][c / 2]);
        float2 p1 = unpack2(acc[1][c / 2]);
        float2 p2 = unpack2(acc[2][c / 2]);
        float2 p3 = unpack2(acc[3][c / 2]);
        float b0 = sB[cb + c], b1v = sB[cb + c + 1];
        float4 v0 = {fmaxf(p0.x + b0, 0.f), fmaxf(p1.x + b0, 0.f),
                     fmaxf(p2.x + b0, 0.f), fmaxf(p3.x + b0, 0.f)};
        float4 v1 = {fmaxf(p0.y + b1v, 0.f), fmaxf(p1.y + b1v, 0.f),
                     fmaxf(p2.y + b1v, 0.f), fmaxf(p3.y + b1v, 0.f)};
        *(float4*)&sH[(cb + c)     * STRIDE + nb] = v0;
        *(float4*)&sH[(cb + c + 1) * STRIDE + nb] = v1;
    }
    __syncthreads();

    // GEMM2: [hw | out_init] = h @ sW2 (k=64)
    unsigned long long acc2[4][4];
#pragma unroll
    for (int n = 0; n < 4; n++)
#pragma unroll
        for (int p = 0; p < 4; p++) acc2[n][p] = 0ull;

#pragma unroll 8
    for (int k = 0; k < HID_C; k++) {
        float4 hv = *(const float4*)&sH[k * STRIDE + nb];
        ulonglong2 w0 = *(const ulonglong2*)&sW2[k * 64 + cb];
        ulonglong2 w1 = *(const ulonglong2*)&sW2[k * 64 + cb + 4];
        float hvf[4] = {hv.x, hv.y, hv.z, hv.w};
#pragma unroll
        for (int n = 0; n < 4; n++) {
            unsigned long long h2 = pack2(hvf[n]);
            fma2(acc2[n][0], h2, w0.x); fma2(acc2[n][1], h2, w0.y);
            fma2(acc2[n][2], h2, w1.x); fma2(acc2[n][3], h2, w1.y);
        }
    }

    // Epilogue: cb<32 -> hw ; cb>=32 -> out = value + b2 (gather2 adds onto it)
    bool to_out = (cb >= 32);
    float* basep = to_out ? outp : hw;
    int coff = to_out ? cb - 32 : cb;
    float add[8];
#pragma unroll
    for (int j = 0; j < 8; j++) add[j] = to_out ? sB2[coff + j] : 0.f;
#pragma unroll
    for (int n = 0; n < 4; n++) {
        int node = nodeBase + nb + n;
        if (node < n_nodes) {
            float2 q0 = unpack2(acc2[n][0]);
            float2 q1 = unpack2(acc2[n][1]);
            float2 q2 = unpack2(acc2[n][2]);
            float2 q3 = unpack2(acc2[n][3]);
            float4 o0 = {q0.x + add[0], q0.y + add[1], q1.x + add[2], q1.y + add[3]};
            float4 o1 = {q2.x + add[4], q2.y + add[5], q3.x + add[6], q3.y + add[7]};
            *(float4*)(basep + (long long)node * OUT_C + coff)     = o0;
            *(float4*)(basep + (long long)node * OUT_C + coff + 4) = o1;
        }
    }
}

// ---------------------------------------------------------------------------
// Launch
// ---------------------------------------------------------------------------
extern "C" void kernel_launch(void* const* d_in, const int* in_sizes, int n_in,
                              void* d_out, int out_size)
{
    const float* x    = (const float*)d_in[0];
    const int*   ei   = (const int*)d_in[1];     // [2, E] int32
    const float* W1l  = (const float*)d_in[2];
    const float* b1   = (const float*)d_in[3];
    const float* W1r  = (const float*)d_in[4];
    const float* W2l  = (const float*)d_in[5];
    const float* b2   = (const float*)d_in[6];
    const float* W2r  = (const float*)d_in[7];
    float*       out  = (float*)d_out;

    const int n_nodes = in_sizes[0] / IN_C;
    const int n_edges = in_sizes[1] / 2;
    const int nchunks = (n_nodes + SCAN_CHUNK - 1) / SCAN_CHUNK;

    const int* src = ei;
    const int* dst = ei + n_edges;

    float *agg1, *hw;
    int *deg, *rowptr, *cursor, *col, *chunkSum;
    cudaGetSymbolAddress((void**)&agg1,     g_agg1);
    cudaGetSymbolAddress((void**)&hw,       g_hw);
    cudaGetSymbolAddress((void**)&deg,      g_deg);
    cudaGetSymbolAddress((void**)&rowptr,   g_rowptr);
    cudaGetSymbolAddress((void**)&cursor,   g_cursor);
    cudaGetSymbolAddress((void**)&col,      g_col);
    cudaGetSymbolAddress((void**)&chunkSum, g_chunkSum);

    // --- CSR build ---
    cudaMemsetAsync(deg, 0, (size_t)n_nodes * sizeof(int));
    deg_count<<<(n_edges + 255) / 256, 256>>>(dst, deg, n_edges);
    scan1<<<nchunks, 256>>>(deg, rowptr, chunkSum, n_nodes);
    scan2b<<<(n_nodes + 255) / 256, 256>>>(rowptr, cursor, chunkSum, n_nodes, nchunks);
    csr_fill<<<(n_edges + 255) / 256, 256>>>(src, dst, cursor, col, n_edges);

    const int gather_blocks = (n_nodes * 32 + 255) / 256;

    // Layer 1 aggregate: raw sums (no memset needed; gather overwrites)
    gather32<false><<<gather_blocks, 256>>>(x, rowptr, col, agg1, n_nodes);

    // Tiled fused transform -> hw, out(=b2+hr)
    {
        const int smem_bytes = (HID_C * STRIDE + 2 * IN_C * HID_C
                              + HID_C * 64 + HID_C + OUT_C) * (int)sizeof(float);
        static bool attr_set = false;
        if (!attr_set) {
            cudaFuncSetAttribute(transform_l1_tiled,
                                 cudaFuncAttributeMaxDynamicSharedMemorySize,
                                 smem_bytes);
            attr_set = true;
        }
        int blocks = (n_nodes + NT - 1) / NT;
        transform_l1_tiled<<<blocks, 256, smem_bytes>>>(
            x, agg1, rowptr, W1l, b1, W1r, W2l, b2, W2r, hw, out, n_nodes);
    }

    // Layer 2 aggregate fused with final combine: out += gather(hw)/deg
    gather32<true><<<gather_blocks, 256>>>(hw, rowptr, col, out, n_nodes);
}